// round 6
// baseline (speedup 1.0000x reference)
#include <cuda_runtime.h>
#include <cuda_fp16.h>
#include <cstdint>

#define H 128

// ---------------------------------------------------------------------------
// Global scratch (no allocations allowed)
// ---------------------------------------------------------------------------
// Per-node layer-1 partials in fp16: [gd_gene | gd_dis | gg_src | gg_dst]
__device__ __half g_Ph[42000000];
// fp16 split weights, transposed: [part][hi/lo][n][k]
// part: 0 = w1_gd[:128], 1 = w1_gg[:128], 2 = w1_gg[128:], 3 = w1_gd[128:]
__device__ __half g_Wh[4 * 2 * H * H];

// ---------------------------------------------------------------------------
// helpers
// ---------------------------------------------------------------------------
__device__ __forceinline__ uint32_t smem_u32(const void* p){
    uint32_t a;
    asm("{ .reg .u64 t; cvta.to.shared.u64 t, %1; cvt.u32.u64 %0, t; }" : "=r"(a) : "l"(p));
    return a;
}
__device__ __forceinline__ void ldsm4(uint32_t* r, uint32_t addr){
    asm volatile("ldmatrix.sync.aligned.m8n8.x4.shared.b16 {%0,%1,%2,%3}, [%4];"
        : "=r"(r[0]), "=r"(r[1]), "=r"(r[2]), "=r"(r[3]) : "r"(addr));
}
__device__ __forceinline__ void mma_f16(float* d, const uint32_t* a,
                                        uint32_t b0, uint32_t b1){
    asm volatile("mma.sync.aligned.m16n8k16.row.col.f32.f16.f16.f32 "
        "{%0,%1,%2,%3}, {%4,%5,%6,%7}, {%8,%9}, {%0,%1,%2,%3};"
        : "+f"(d[0]), "+f"(d[1]), "+f"(d[2]), "+f"(d[3])
        : "r"(a[0]), "r"(a[1]), "r"(a[2]), "r"(a[3]), "r"(b0), "r"(b1));
}

// XOR-swizzled byte offset inside a [128 rows x 128 fp16] tile (256B rows).
__device__ __forceinline__ uint32_t toff(int r, int kc){
    return (uint32_t)r * 256u + (uint32_t)((kc ^ (r & 7)) << 4);
}

// smem map: A 32KB | B-hi 32KB | B-lo 32KB
#define SM_A  0
#define SM_BH 32768
#define SM_BL 65536
#define SM_TOTAL 98304

// ---------------------------------------------------------------------------
// Kernel 0: split+transpose the four 128x128 W blocks -> fp16 hi/lo, [n][k]
// ---------------------------------------------------------------------------
__global__ void prep_w_kernel(const float* __restrict__ w1_gd,
                              const float* __restrict__ w1_gg)
{
    int idx = blockIdx.x * blockDim.x + threadIdx.x;  // 4*128*128
    if (idx >= 4 * H * H) return;
    int part = idx >> 14;
    int n = (idx >> 7) & 127;
    int k = idx & 127;
    const float* Wsrc = (part == 0) ? w1_gd
                      : (part == 1) ? w1_gg
                      : (part == 2) ? (w1_gg + H * H)
                                    : (w1_gd + H * H);
    float x = Wsrc[k * H + n];
    __half hi = __float2half_rn(x);
    __half lo = __float2half_rn(x - __half2float(hi));
    g_Wh[((size_t)(part * 2 + 0) * H + n) * H + k] = hi;
    g_Wh[((size_t)(part * 2 + 1) * H + n) * H + k] = lo;
}

// ---------------------------------------------------------------------------
// Kernel 1: tensor-core GEMM via mma.sync fp16, 2-pass weight split.
// mode 0: gene tiles -> part 0, disease tiles -> part 3  (gd partials)
// mode 1: gene tiles -> parts 1 then 2 (A staged once)   (gg partials)
// ---------------------------------------------------------------------------
__global__ void __launch_bounds__(256, 2)
gemm_tc_kernel(const float* __restrict__ zg, const float* __restrict__ zd,
               const float* __restrict__ b1_gd, const float* __restrict__ b1_gg,
               int n_gene, int n_dis, int mode)
{
    extern __shared__ char smem[];
    const uint32_t sb = smem_u32(smem);
    const int tid = threadIdx.x;

    const int tg = (n_gene + 127) >> 7;
    const size_t ng = (size_t)n_gene * H, nd = (size_t)n_dis * H;

    const int b = blockIdx.x;
    const bool isGene = (mode == 1) || (b < tg);
    const float* A = isGene ? zg : zd;
    const int M = isGene ? n_gene : n_dis;
    const int m0 = (isGene ? b : (b - tg)) << 7;

    int plist[2]; int nparts;
    if (mode == 0) { plist[0] = isGene ? 0 : 3; nparts = 1; }
    else           { plist[0] = 1; plist[1] = 2; nparts = 2; }

    // ---- stage A (fp32 -> fp16 hi) once ----
    #pragma unroll
    for (int i = 0; i < 8; i++) {
        int u = tid + 256 * i;
        int r = u >> 4, c8 = u & 15;
        float4 v0 = make_float4(0.f,0.f,0.f,0.f), v1 = v0;
        if (m0 + r < M) {
            const float* ap = &A[(size_t)(m0 + r) * H + c8 * 8];
            v0 = *(const float4*)ap;
            v1 = *(const float4*)(ap + 4);
        }
        __half2 h0 = __floats2half2_rn(v0.x, v0.y);
        __half2 h1 = __floats2half2_rn(v0.z, v0.w);
        __half2 h2 = __floats2half2_rn(v1.x, v1.y);
        __half2 h3 = __floats2half2_rn(v1.z, v1.w);
        uint4 pk = make_uint4(*(uint32_t*)&h0, *(uint32_t*)&h1,
                              *(uint32_t*)&h2, *(uint32_t*)&h3);
        *(uint4*)(smem + SM_A + toff(r, c8)) = pk;
    }

    const int lane = tid & 31, w = tid >> 5;
    const int wr = w >> 1, wc = w & 1;
    const int arow = wr * 32 + (lane & 15);
    const int akh  = lane >> 4;
    const int brow = wc * 64 + (lane & 7) + ((lane >> 4) << 3);
    const int bkh  = (lane >> 3) & 1;
    const int rbase = m0 + wr * 32 + (lane >> 2);
    const int cbase = wc * 64 + (lane & 3) * 2;

    for (int p = 0; p < nparts; p++) {
        const int part = plist[p];
        const float* bias = (part == 2) ? b1_gg : (part == 3) ? b1_gd : nullptr;
        const size_t outOff = (part == 0) ? 0
                            : (part == 1) ? (ng + nd)
                            : (part == 2) ? (ng + nd + ng)
                                          : ng;

        // ---- stage B hi/lo for this part ----
        {
            const uint4* bh = (const uint4*)(g_Wh + (size_t)(part * 2 + 0) * H * H);
            const uint4* bl = (const uint4*)(g_Wh + (size_t)(part * 2 + 1) * H * H);
            #pragma unroll
            for (int i = 0; i < 8; i++) {
                int u = tid + 256 * i;
                int r = u >> 4, kc = u & 15;
                uint32_t o = toff(r, kc);
                *(uint4*)(smem + SM_BH + o) = bh[u];
                *(uint4*)(smem + SM_BL + o) = bl[u];
            }
        }
        __syncthreads();

        // ---- compute ----
        float acc[2][8][4];
        #pragma unroll
        for (int mt = 0; mt < 2; mt++)
            #pragma unroll
            for (int nt = 0; nt < 8; nt++)
                #pragma unroll
                for (int q = 0; q < 4; q++) acc[mt][nt][q] = 0.f;

        #pragma unroll
        for (int s = 0; s < 8; s++) {
            uint32_t afr[2][4];
            #pragma unroll
            for (int mt = 0; mt < 2; mt++)
                ldsm4(afr[mt], sb + SM_A + toff(arow + mt * 16, 2 * s + akh));

            uint32_t bfr[4][4];
            #pragma unroll
            for (int np = 0; np < 4; np++)
                ldsm4(bfr[np], sb + SM_BH + toff(brow + np * 16, 2 * s + bkh));
            #pragma unroll
            for (int mt = 0; mt < 2; mt++)
                #pragma unroll
                for (int nt = 0; nt < 8; nt++)
                    mma_f16(acc[mt][nt], afr[mt],
                            bfr[nt >> 1][(nt & 1) * 2], bfr[nt >> 1][(nt & 1) * 2 + 1]);

            #pragma unroll
            for (int np = 0; np < 4; np++)
                ldsm4(bfr[np], sb + SM_BL + toff(brow + np * 16, 2 * s + bkh));
            #pragma unroll
            for (int mt = 0; mt < 2; mt++)
                #pragma unroll
                for (int nt = 0; nt < 8; nt++)
                    mma_f16(acc[mt][nt], afr[mt],
                            bfr[nt >> 1][(nt & 1) * 2], bfr[nt >> 1][(nt & 1) * 2 + 1]);
        }

        // ---- writeout (fp16) ----
        #pragma unroll
        for (int mt = 0; mt < 2; mt++) {
            #pragma unroll
            for (int nt = 0; nt < 8; nt++) {
                int n = cbase + nt * 8;
                float bx = 0.f, by = 0.f;
                if (bias) { float2 bv = *(const float2*)&bias[n]; bx = bv.x; by = bv.y; }
                int rr0 = rbase + mt * 16;
                int rr1 = rr0 + 8;
                if (rr0 < M) {
                    __half2 o0 = __floats2half2_rn(acc[mt][nt][0] + bx, acc[mt][nt][1] + by);
                    *(__half2*)&g_Ph[outOff + (size_t)rr0 * H + n] = o0;
                }
                if (rr1 < M) {
                    __half2 o1 = __floats2half2_rn(acc[mt][nt][2] + bx, acc[mt][nt][3] + by);
                    *(__half2*)&g_Ph[outOff + (size_t)rr1 * H + n] = o1;
                }
            }
        }
        if (p + 1 < nparts) __syncthreads();
    }
}

// ---------------------------------------------------------------------------
// Kernel 2: per-edge combine on fp16 partials, one relation per launch.
// ---------------------------------------------------------------------------
__global__ void __launch_bounds__(256)
edge_decode_kernel(const int* __restrict__ edges,
                   const float* __restrict__ w2, const float* __restrict__ b2p,
                   float* __restrict__ o, int E, int rel, int n_gene, int n_dis)
{
    const size_t ng = (size_t)n_gene * H;
    const size_t nd = (size_t)n_dis * H;

    const __half* Psrc = rel ? (g_Ph + ng + nd)      : g_Ph;
    const __half* Pdst = rel ? (g_Ph + ng + nd + ng) : (g_Ph + ng);
    const float  b2    = b2p[0];

    const int lane   = threadIdx.x & 31;
    const int warp   = (blockIdx.x * blockDim.x + threadIdx.x) >> 5;
    const int nwarps = (gridDim.x * blockDim.x) >> 5;

    const float4 w = *(const float4*)&w2[lane * 4];

    for (int e = warp; e < E; e += 2 * nwarps) {
        const int e1 = e + nwarps;
        const bool has2 = e1 < E;

        const int s0 = edges[e], d0 = edges[E + e];
        uint2 ua0 = *(const uint2*)&Psrc[(size_t)s0 * H + lane * 4];
        uint2 ub0 = *(const uint2*)&Pdst[(size_t)d0 * H + lane * 4];

        uint2 ua1 = make_uint2(0u, 0u), ub1 = ua1;
        if (has2) {
            const int s1 = edges[e1], d1 = edges[E + e1];
            ua1 = *(const uint2*)&Psrc[(size_t)s1 * H + lane * 4];
            ub1 = *(const uint2*)&Pdst[(size_t)d1 * H + lane * 4];
        }

        float2 fa0 = __half22float2(*(__half2*)&ua0.x);
        float2 fa1 = __half22float2(*(__half2*)&ua0.y);
        float2 fb0 = __half22float2(*(__half2*)&ub0.x);
        float2 fb1 = __half22float2(*(__half2*)&ub0.y);
        float sum0;
        sum0  = fmaxf(fa0.x + fb0.x, 0.f) * w.x;
        sum0 += fmaxf(fa0.y + fb0.y, 0.f) * w.y;
        sum0 += fmaxf(fa1.x + fb1.x, 0.f) * w.z;
        sum0 += fmaxf(fa1.y + fb1.y, 0.f) * w.w;
        #pragma unroll
        for (int off = 16; off; off >>= 1)
            sum0 += __shfl_xor_sync(0xFFFFFFFFu, sum0, off);
        if (lane == 0) o[e] = sum0 + b2;

        if (has2) {
            float2 ga0 = __half22float2(*(__half2*)&ua1.x);
            float2 ga1 = __half22float2(*(__half2*)&ua1.y);
            float2 gb0 = __half22float2(*(__half2*)&ub1.x);
            float2 gb1 = __half22float2(*(__half2*)&ub1.y);
            float sum1;
            sum1  = fmaxf(ga0.x + gb0.x, 0.f) * w.x;
            sum1 += fmaxf(ga0.y + gb0.y, 0.f) * w.y;
            sum1 += fmaxf(ga1.x + gb1.x, 0.f) * w.z;
            sum1 += fmaxf(ga1.y + gb1.y, 0.f) * w.w;
            #pragma unroll
            for (int off = 16; off; off >>= 1)
                sum1 += __shfl_xor_sync(0xFFFFFFFFu, sum1, off);
            if (lane == 0) o[e1] = sum1 + b2;
        }
    }
}

// ---------------------------------------------------------------------------
extern "C" void kernel_launch(void* const* d_in, const int* in_sizes, int n_in,
                              void* d_out, int out_size)
{
    const float* z_gene = (const float*)d_in[0];
    const float* z_dis  = (const float*)d_in[1];
    const int*   e_gd   = (const int*)  d_in[2];
    const int*   e_gg   = (const int*)  d_in[3];
    const float* w1_gd  = (const float*)d_in[4];
    const float* b1_gd  = (const float*)d_in[5];
    const float* w2_gd  = (const float*)d_in[6];
    const float* b2_gd  = (const float*)d_in[7];
    const float* w1_gg  = (const float*)d_in[8];
    const float* b1_gg  = (const float*)d_in[9];
    const float* w2_gg  = (const float*)d_in[10];
    const float* b2_gg  = (const float*)d_in[11];

    const int n_gene = in_sizes[0] / H;
    const int n_dis  = in_sizes[1] / H;
    const int E      = in_sizes[2] / 2;

    static cudaStream_t s1;
    static cudaEvent_t evA, evJ;
    static bool init_done = false;
    if (!init_done) {
        cudaFuncSetAttribute(gemm_tc_kernel,
                             cudaFuncAttributeMaxDynamicSharedMemorySize, SM_TOTAL);
        cudaStreamCreateWithFlags(&s1, cudaStreamNonBlocking);
        cudaEventCreateWithFlags(&evA, cudaEventDisableTiming);
        cudaEventCreateWithFlags(&evJ, cudaEventDisableTiming);
        init_done = true;
    }

    const int tg = (n_gene + 127) >> 7;
    const int td = (n_dis + 127) >> 7;
    float* out = (float*)d_out;

    // s0: prep -> gemmA (gd partials: parts 0,3)
    prep_w_kernel<<<(4 * H * H + 255) / 256, 256>>>(w1_gd, w1_gg);
    gemm_tc_kernel<<<tg + td, 256, SM_TOTAL>>>(z_gene, z_dis, b1_gd, b1_gg,
                                               n_gene, n_dis, 0);
    cudaEventRecord(evA, 0);

    // s1: edge_gd overlapped with gemmB on s0
    cudaStreamWaitEvent(s1, evA, 0);
    edge_decode_kernel<<<1184, 256, 0, s1>>>(e_gd, w2_gd, b2_gd, out,
                                             E, 0, n_gene, n_dis);
    cudaEventRecord(evJ, s1);

    // s0: gemmB (gg partials: parts 1,2) -> edge_gg
    gemm_tc_kernel<<<tg, 256, SM_TOTAL>>>(z_gene, z_dis, b1_gd, b1_gg,
                                          n_gene, n_dis, 1);
    edge_decode_kernel<<<1184, 256>>>(e_gg, w2_gg, b2_gg, out + (size_t)E,
                                      E, 1, n_gene, n_dis);

    // join s1 back into the capture stream
    cudaStreamWaitEvent(0, evJ, 0);
}

// round 7
// speedup vs baseline: 1.2179x; 1.2179x over previous
#include <cuda_runtime.h>
#include <cuda_fp16.h>
#include <cstdint>

#define H 128

// ---------------------------------------------------------------------------
// Global scratch (no allocations allowed)
// ---------------------------------------------------------------------------
// Per-node layer-1 partials in fp16: [gd_gene | gd_dis | gg_src | gg_dst]
__device__ __half g_Ph[42000000];
// fp16 weights (rounded), transposed: [part][n][k]
// part: 0 = w1_gd[:128], 1 = w1_gg[:128], 2 = w1_gg[128:], 3 = w1_gd[128:]
__device__ __half g_Wh[4 * H * H];

// ---------------------------------------------------------------------------
// helpers
// ---------------------------------------------------------------------------
__device__ __forceinline__ uint32_t smem_u32(const void* p){
    uint32_t a;
    asm("{ .reg .u64 t; cvta.to.shared.u64 t, %1; cvt.u32.u64 %0, t; }" : "=r"(a) : "l"(p));
    return a;
}
__device__ __forceinline__ void ldsm4(uint32_t* r, uint32_t addr){
    asm volatile("ldmatrix.sync.aligned.m8n8.x4.shared.b16 {%0,%1,%2,%3}, [%4];"
        : "=r"(r[0]), "=r"(r[1]), "=r"(r[2]), "=r"(r[3]) : "r"(addr));
}
__device__ __forceinline__ void mma_f16(float* d, const uint32_t* a,
                                        uint32_t b0, uint32_t b1){
    asm volatile("mma.sync.aligned.m16n8k16.row.col.f32.f16.f16.f32 "
        "{%0,%1,%2,%3}, {%4,%5,%6,%7}, {%8,%9}, {%0,%1,%2,%3};"
        : "+f"(d[0]), "+f"(d[1]), "+f"(d[2]), "+f"(d[3])
        : "r"(a[0]), "r"(a[1]), "r"(a[2]), "r"(a[3]), "r"(b0), "r"(b1));
}

// XOR-swizzled byte offset inside a [128 rows x 128 fp16] tile (256B rows).
__device__ __forceinline__ uint32_t toff(int r, int kc){
    return (uint32_t)r * 256u + (uint32_t)((kc ^ (r & 7)) << 4);
}

// smem map: A 32KB | B 32KB
#define SM_A  0
#define SM_B  32768
#define SM_TOTAL 65536

// ---------------------------------------------------------------------------
// Kernel 0: round+transpose the four 128x128 W blocks -> fp16, [n][k]
// ---------------------------------------------------------------------------
__global__ void prep_w_kernel(const float* __restrict__ w1_gd,
                              const float* __restrict__ w1_gg)
{
    int idx = blockIdx.x * blockDim.x + threadIdx.x;  // 4*128*128
    if (idx >= 4 * H * H) return;
    int part = idx >> 14;
    int n = (idx >> 7) & 127;
    int k = idx & 127;
    const float* Wsrc = (part == 0) ? w1_gd
                      : (part == 1) ? w1_gg
                      : (part == 2) ? (w1_gg + H * H)
                                    : (w1_gd + H * H);
    g_Wh[((size_t)part * H + n) * H + k] = __float2half_rn(Wsrc[k * H + n]);
}

// ---------------------------------------------------------------------------
// Kernel 1: single-pass fp16 tensor-core GEMM. A staged ONCE per tile;
// gene tiles loop parts 0,1,2; disease tiles do part 3 only.
// C = A_hi @ B_hi^T (fp32 accum), + bias, fp16 out.
// ---------------------------------------------------------------------------
__global__ void __launch_bounds__(256, 2)
gemm_tc_kernel(const float* __restrict__ zg, const float* __restrict__ zd,
               const float* __restrict__ b1_gd, const float* __restrict__ b1_gg,
               int n_gene, int n_dis)
{
    extern __shared__ char smem[];
    const uint32_t sb = smem_u32(smem);
    const int tid = threadIdx.x;

    const int tg = (n_gene + 127) >> 7;
    const size_t ng = (size_t)n_gene * H, nd = (size_t)n_dis * H;

    const int b = blockIdx.x;
    const bool isGene = (b < tg);
    const float* A = isGene ? zg : zd;
    const int M = isGene ? n_gene : n_dis;
    const int m0 = (isGene ? b : (b - tg)) << 7;
    const int nparts = isGene ? 3 : 1;

    // ---- stage A (fp32 -> fp16) once ----
    #pragma unroll
    for (int i = 0; i < 8; i++) {
        int u = tid + 256 * i;
        int r = u >> 4, c8 = u & 15;
        float4 v0 = make_float4(0.f,0.f,0.f,0.f), v1 = v0;
        if (m0 + r < M) {
            const float* ap = &A[(size_t)(m0 + r) * H + c8 * 8];
            v0 = *(const float4*)ap;
            v1 = *(const float4*)(ap + 4);
        }
        __half2 h0 = __floats2half2_rn(v0.x, v0.y);
        __half2 h1 = __floats2half2_rn(v0.z, v0.w);
        __half2 h2 = __floats2half2_rn(v1.x, v1.y);
        __half2 h3 = __floats2half2_rn(v1.z, v1.w);
        uint4 pk = make_uint4(*(uint32_t*)&h0, *(uint32_t*)&h1,
                              *(uint32_t*)&h2, *(uint32_t*)&h3);
        *(uint4*)(smem + SM_A + toff(r, c8)) = pk;
    }

    const int lane = tid & 31, w = tid >> 5;
    const int wr = w >> 1, wc = w & 1;
    const int arow = wr * 32 + (lane & 15);
    const int akh  = lane >> 4;
    const int brow = wc * 64 + (lane & 7) + ((lane >> 4) << 3);
    const int bkh  = (lane >> 3) & 1;
    const int rbase = m0 + wr * 32 + (lane >> 2);
    const int cbase = wc * 64 + (lane & 3) * 2;

    for (int p = 0; p < nparts; p++) {
        const int part = isGene ? p : 3;
        const float* bias = (part == 2) ? b1_gg : (part == 3) ? b1_gd : nullptr;
        const size_t outOff = (part == 0) ? 0
                            : (part == 1) ? (ng + nd)
                            : (part == 2) ? (ng + nd + ng)
                                          : ng;

        // ---- stage B for this part (4 uint4 per thread = 32KB) ----
        {
            const uint4* bp = (const uint4*)(g_Wh + (size_t)part * H * H);
            #pragma unroll
            for (int i = 0; i < 4; i++) {
                int u = tid + 256 * i;          // 0..1023
                int r = u >> 3, kc = u & 7;     // 8 chunks of 16B per 128-fp16... no:
                // [128 rows x 128 fp16] = 16 chunks/row, 2048 chunks; 4/thread? No:
                // 32KB / 16B = 2048 chunks -> 8 per thread. Recompute below.
                (void)r; (void)kc; (void)bp;
            }
            // correct staging: 2048 16B-chunks, 8 per thread
            #pragma unroll
            for (int i = 0; i < 8; i++) {
                int u = tid + 256 * i;
                int r = u >> 4, kc = u & 15;
                *(uint4*)(smem + SM_B + toff(r, kc)) = bp[u];
            }
        }
        __syncthreads();

        // ---- compute ----
        float acc[2][8][4];
        #pragma unroll
        for (int mt = 0; mt < 2; mt++)
            #pragma unroll
            for (int nt = 0; nt < 8; nt++)
                #pragma unroll
                for (int q = 0; q < 4; q++) acc[mt][nt][q] = 0.f;

        #pragma unroll
        for (int s = 0; s < 8; s++) {
            uint32_t afr[2][4];
            #pragma unroll
            for (int mt = 0; mt < 2; mt++)
                ldsm4(afr[mt], sb + SM_A + toff(arow + mt * 16, 2 * s + akh));

            uint32_t bfr[4][4];
            #pragma unroll
            for (int np = 0; np < 4; np++)
                ldsm4(bfr[np], sb + SM_B + toff(brow + np * 16, 2 * s + bkh));

            #pragma unroll
            for (int mt = 0; mt < 2; mt++)
                #pragma unroll
                for (int nt = 0; nt < 8; nt++)
                    mma_f16(acc[mt][nt], afr[mt],
                            bfr[nt >> 1][(nt & 1) * 2], bfr[nt >> 1][(nt & 1) * 2 + 1]);
        }

        // ---- writeout (fp16) ----
        #pragma unroll
        for (int mt = 0; mt < 2; mt++) {
            #pragma unroll
            for (int nt = 0; nt < 8; nt++) {
                int n = cbase + nt * 8;
                float bx = 0.f, by = 0.f;
                if (bias) { float2 bv = *(const float2*)&bias[n]; bx = bv.x; by = bv.y; }
                int rr0 = rbase + mt * 16;
                int rr1 = rr0 + 8;
                if (rr0 < M) {
                    __half2 o0 = __floats2half2_rn(acc[mt][nt][0] + bx, acc[mt][nt][1] + by);
                    *(__half2*)&g_Ph[outOff + (size_t)rr0 * H + n] = o0;
                }
                if (rr1 < M) {
                    __half2 o1 = __floats2half2_rn(acc[mt][nt][2] + bx, acc[mt][nt][3] + by);
                    *(__half2*)&g_Ph[outOff + (size_t)rr1 * H + n] = o1;
                }
            }
        }
        if (p + 1 < nparts) __syncthreads();
    }
}

// ---------------------------------------------------------------------------
// Kernel 2: per-edge combine on fp16 partials. One warp per edge, x2 ILP.
// ---------------------------------------------------------------------------
__global__ void __launch_bounds__(256)
edge_decode_kernel(const int* __restrict__ edges_gd, const int* __restrict__ edges_gg,
                   const float* __restrict__ w2_gd, const float* __restrict__ b2_gd,
                   const float* __restrict__ w2_gg, const float* __restrict__ b2_gg,
                   float* __restrict__ out, int E, int n_gene, int n_dis)
{
    const int rel = blockIdx.y;
    const size_t ng = (size_t)n_gene * H;
    const size_t nd = (size_t)n_dis * H;

    const int*   edges = rel ? edges_gg : edges_gd;
    const __half* Psrc = rel ? (g_Ph + ng + nd)      : g_Ph;
    const __half* Pdst = rel ? (g_Ph + ng + nd + ng) : (g_Ph + ng);
    const float* w2    = rel ? w2_gg : w2_gd;
    const float  b2    = (rel ? b2_gg : b2_gd)[0];
    float* o = out + (size_t)rel * E;

    const int lane   = threadIdx.x & 31;
    const int warp   = (blockIdx.x * blockDim.x + threadIdx.x) >> 5;
    const int nwarps = (gridDim.x * blockDim.x) >> 5;

    const float4 w = *(const float4*)&w2[lane * 4];

    for (int e = warp; e < E; e += 2 * nwarps) {
        const int e1 = e + nwarps;
        const bool has2 = e1 < E;

        const int s0 = edges[e], d0 = edges[E + e];
        uint2 ua0 = *(const uint2*)&Psrc[(size_t)s0 * H + lane * 4];
        uint2 ub0 = *(const uint2*)&Pdst[(size_t)d0 * H + lane * 4];

        uint2 ua1 = make_uint2(0u, 0u), ub1 = ua1;
        if (has2) {
            const int s1 = edges[e1], d1 = edges[E + e1];
            ua1 = *(const uint2*)&Psrc[(size_t)s1 * H + lane * 4];
            ub1 = *(const uint2*)&Pdst[(size_t)d1 * H + lane * 4];
        }

        float2 fa0 = __half22float2(*(__half2*)&ua0.x);
        float2 fa1 = __half22float2(*(__half2*)&ua0.y);
        float2 fb0 = __half22float2(*(__half2*)&ub0.x);
        float2 fb1 = __half22float2(*(__half2*)&ub0.y);
        float sum0;
        sum0  = fmaxf(fa0.x + fb0.x, 0.f) * w.x;
        sum0 += fmaxf(fa0.y + fb0.y, 0.f) * w.y;
        sum0 += fmaxf(fa1.x + fb1.x, 0.f) * w.z;
        sum0 += fmaxf(fa1.y + fb1.y, 0.f) * w.w;
        #pragma unroll
        for (int off = 16; off; off >>= 1)
            sum0 += __shfl_xor_sync(0xFFFFFFFFu, sum0, off);
        if (lane == 0) o[e] = sum0 + b2;

        if (has2) {
            float2 ga0 = __half22float2(*(__half2*)&ua1.x);
            float2 ga1 = __half22float2(*(__half2*)&ua1.y);
            float2 gb0 = __half22float2(*(__half2*)&ub1.x);
            float2 gb1 = __half22float2(*(__half2*)&ub1.y);
            float sum1;
            sum1  = fmaxf(ga0.x + gb0.x, 0.f) * w.x;
            sum1 += fmaxf(ga0.y + gb0.y, 0.f) * w.y;
            sum1 += fmaxf(ga1.x + gb1.x, 0.f) * w.z;
            sum1 += fmaxf(ga1.y + gb1.y, 0.f) * w.w;
            #pragma unroll
            for (int off = 16; off; off >>= 1)
                sum1 += __shfl_xor_sync(0xFFFFFFFFu, sum1, off);
            if (lane == 0) o[e1] = sum1 + b2;
        }
    }
}

// ---------------------------------------------------------------------------
extern "C" void kernel_launch(void* const* d_in, const int* in_sizes, int n_in,
                              void* d_out, int out_size)
{
    const float* z_gene = (const float*)d_in[0];
    const float* z_dis  = (const float*)d_in[1];
    const int*   e_gd   = (const int*)  d_in[2];
    const int*   e_gg   = (const int*)  d_in[3];
    const float* w1_gd  = (const float*)d_in[4];
    const float* b1_gd  = (const float*)d_in[5];
    const float* w2_gd  = (const float*)d_in[6];
    const float* b2_gd  = (const float*)d_in[7];
    const float* w1_gg  = (const float*)d_in[8];
    const float* b1_gg  = (const float*)d_in[9];
    const float* w2_gg  = (const float*)d_in[10];
    const float* b2_gg  = (const float*)d_in[11];

    const int n_gene = in_sizes[0] / H;
    const int n_dis  = in_sizes[1] / H;
    const int E      = in_sizes[2] / 2;

    static bool init_done = false;
    if (!init_done) {
        cudaFuncSetAttribute(gemm_tc_kernel,
                             cudaFuncAttributeMaxDynamicSharedMemorySize, SM_TOTAL);
        init_done = true;
    }

    prep_w_kernel<<<(4 * H * H + 255) / 256, 256>>>(w1_gd, w1_gg);

    const int tg = (n_gene + 127) >> 7;
    const int td = (n_dis + 127) >> 7;
    gemm_tc_kernel<<<tg + td, 256, SM_TOTAL>>>(z_gene, z_dis, b1_gd, b1_gg,
                                               n_gene, n_dis);

    dim3 egrid(1184, 2);
    edge_decode_kernel<<<egrid, 256>>>(e_gd, e_gg, w2_gd, b2_gd, w2_gg, b2_gg,
                                       (float*)d_out, E, n_gene, n_dis);
}

// round 8
// speedup vs baseline: 1.2377x; 1.0163x over previous
#include <cuda_runtime.h>
#include <cuda_fp16.h>
#include <cstdint>

#define H 128

// ---------------------------------------------------------------------------
// Global scratch (no allocations allowed)
// ---------------------------------------------------------------------------
// Per-node layer-1 partials in fp16: [gd_gene | gd_dis | gg_src | gg_dst]
__device__ __half g_Ph[42000000];
// fp16 weights (rounded), transposed: [part][n][k]
// part: 0 = w1_gd[:128], 1 = w1_gg[:128], 2 = w1_gg[128:], 3 = w1_gd[128:]
__device__ __half g_Wh[4 * H * H];

// ---------------------------------------------------------------------------
// helpers
// ---------------------------------------------------------------------------
__device__ __forceinline__ uint32_t smem_u32(const void* p){
    uint32_t a;
    asm("{ .reg .u64 t; cvta.to.shared.u64 t, %1; cvt.u32.u64 %0, t; }" : "=r"(a) : "l"(p));
    return a;
}
__device__ __forceinline__ void ldsm4(uint32_t* r, uint32_t addr){
    asm volatile("ldmatrix.sync.aligned.m8n8.x4.shared.b16 {%0,%1,%2,%3}, [%4];"
        : "=r"(r[0]), "=r"(r[1]), "=r"(r[2]), "=r"(r[3]) : "r"(addr));
}
__device__ __forceinline__ void mma_f16(float* d, const uint32_t* a,
                                        uint32_t b0, uint32_t b1){
    asm volatile("mma.sync.aligned.m16n8k16.row.col.f32.f16.f16.f32 "
        "{%0,%1,%2,%3}, {%4,%5,%6,%7}, {%8,%9}, {%0,%1,%2,%3};"
        : "+f"(d[0]), "+f"(d[1]), "+f"(d[2]), "+f"(d[3])
        : "r"(a[0]), "r"(a[1]), "r"(a[2]), "r"(a[3]), "r"(b0), "r"(b1));
}

// XOR-swizzled byte offset inside a [128 rows x 128 fp16] tile (256B rows).
__device__ __forceinline__ uint32_t toff(int r, int kc){
    return (uint32_t)r * 256u + (uint32_t)((kc ^ (r & 7)) << 4);
}

// smem map: A 32KB | B 32KB
#define SM_A  0
#define SM_B  32768
#define SM_TOTAL 65536

// ---------------------------------------------------------------------------
// Kernel 0: round+transpose the four 128x128 W blocks -> fp16, [n][k]
// ---------------------------------------------------------------------------
__global__ void prep_w_kernel(const float* __restrict__ w1_gd,
                              const float* __restrict__ w1_gg)
{
    int idx = blockIdx.x * blockDim.x + threadIdx.x;  // 4*128*128
    if (idx >= 4 * H * H) return;
    int part = idx >> 14;
    int n = (idx >> 7) & 127;
    int k = idx & 127;
    const float* Wsrc = (part == 0) ? w1_gd
                      : (part == 1) ? w1_gg
                      : (part == 2) ? (w1_gg + H * H)
                                    : (w1_gd + H * H);
    g_Wh[((size_t)part * H + n) * H + k] = __float2half_rn(Wsrc[k * H + n]);
}

// ---------------------------------------------------------------------------
// Kernel 1: single-pass fp16 GEMM, 512 threads, 16 warps x (32x32) warp tile.
// Low-reg layout -> 2 CTAs/SM -> 32 warps resident.
// ---------------------------------------------------------------------------
__global__ void __launch_bounds__(512, 2)
gemm_tc_kernel(const float* __restrict__ zg, const float* __restrict__ zd,
               const float* __restrict__ b1_gd, const float* __restrict__ b1_gg,
               int n_gene, int n_dis)
{
    extern __shared__ char smem[];
    const uint32_t sb = smem_u32(smem);
    const int tid = threadIdx.x;

    const int tg = (n_gene + 127) >> 7;
    const size_t ng = (size_t)n_gene * H, nd = (size_t)n_dis * H;

    const int b = blockIdx.x;
    const bool isGene = (b < tg);
    const float* A = isGene ? zg : zd;
    const int M = isGene ? n_gene : n_dis;
    const int m0 = (isGene ? b : (b - tg)) << 7;
    const int nparts = isGene ? 3 : 1;

    // ---- stage A (fp32 -> fp16) once: 2048 16B chunks, 4 per thread ----
    #pragma unroll
    for (int i = 0; i < 4; i++) {
        int u = tid + 512 * i;
        int r = u >> 4, c8 = u & 15;
        float4 v0 = make_float4(0.f,0.f,0.f,0.f), v1 = v0;
        if (m0 + r < M) {
            const float* ap = &A[(size_t)(m0 + r) * H + c8 * 8];
            v0 = *(const float4*)ap;
            v1 = *(const float4*)(ap + 4);
        }
        __half2 h0 = __floats2half2_rn(v0.x, v0.y);
        __half2 h1 = __floats2half2_rn(v0.z, v0.w);
        __half2 h2 = __floats2half2_rn(v1.x, v1.y);
        __half2 h3 = __floats2half2_rn(v1.z, v1.w);
        uint4 pk = make_uint4(*(uint32_t*)&h0, *(uint32_t*)&h1,
                              *(uint32_t*)&h2, *(uint32_t*)&h3);
        *(uint4*)(smem + SM_A + toff(r, c8)) = pk;
    }

    const int lane = tid & 31, w = tid >> 5;
    const int wr = w >> 2, wc = w & 3;          // 4x4 warp grid, 32x32 tiles
    const int arow = wr * 32 + (lane & 15);
    const int akh  = lane >> 4;
    const int brow = wc * 32 + (lane & 7) + ((lane >> 4) << 3);
    const int bkh  = (lane >> 3) & 1;
    const int rbase = m0 + wr * 32 + (lane >> 2);
    const int cbase = wc * 32 + (lane & 3) * 2;

    for (int p = 0; p < nparts; p++) {
        const int part = isGene ? p : 3;
        const float* bias = (part == 2) ? b1_gg : (part == 3) ? b1_gd : nullptr;
        const size_t outOff = (part == 0) ? 0
                            : (part == 1) ? (ng + nd)
                            : (part == 2) ? (ng + nd + ng)
                                          : ng;

        // ---- stage B for this part: 2048 chunks, 4 per thread ----
        {
            const uint4* bp = (const uint4*)(g_Wh + (size_t)part * H * H);
            #pragma unroll
            for (int i = 0; i < 4; i++) {
                int u = tid + 512 * i;
                int r = u >> 4, kc = u & 15;
                *(uint4*)(smem + SM_B + toff(r, kc)) = bp[u];
            }
        }
        __syncthreads();

        // ---- compute: 32x32 warp tile ----
        float acc[2][4][4];
        #pragma unroll
        for (int mt = 0; mt < 2; mt++)
            #pragma unroll
            for (int nt = 0; nt < 4; nt++)
                #pragma unroll
                for (int q = 0; q < 4; q++) acc[mt][nt][q] = 0.f;

        #pragma unroll
        for (int s = 0; s < 8; s++) {
            uint32_t afr[2][4];
            #pragma unroll
            for (int mt = 0; mt < 2; mt++)
                ldsm4(afr[mt], sb + SM_A + toff(arow + mt * 16, 2 * s + akh));

            uint32_t bfr[2][4];
            #pragma unroll
            for (int np = 0; np < 2; np++)
                ldsm4(bfr[np], sb + SM_B + toff(brow + np * 16, 2 * s + bkh));

            #pragma unroll
            for (int mt = 0; mt < 2; mt++)
                #pragma unroll
                for (int nt = 0; nt < 4; nt++)
                    mma_f16(acc[mt][nt], afr[mt],
                            bfr[nt >> 1][(nt & 1) * 2], bfr[nt >> 1][(nt & 1) * 2 + 1]);
        }

        // ---- writeout (fp16) ----
        #pragma unroll
        for (int mt = 0; mt < 2; mt++) {
            #pragma unroll
            for (int nt = 0; nt < 4; nt++) {
                int n = cbase + nt * 8;
                float bx = 0.f, by = 0.f;
                if (bias) { float2 bv = *(const float2*)&bias[n]; bx = bv.x; by = bv.y; }
                int rr0 = rbase + mt * 16;
                int rr1 = rr0 + 8;
                if (rr0 < M) {
                    __half2 o0 = __floats2half2_rn(acc[mt][nt][0] + bx, acc[mt][nt][1] + by);
                    *(__half2*)&g_Ph[outOff + (size_t)rr0 * H + n] = o0;
                }
                if (rr1 < M) {
                    __half2 o1 = __floats2half2_rn(acc[mt][nt][2] + bx, acc[mt][nt][3] + by);
                    *(__half2*)&g_Ph[outOff + (size_t)rr1 * H + n] = o1;
                }
            }
        }
        if (p + 1 < nparts) __syncthreads();
    }
}

// ---------------------------------------------------------------------------
// Kernel 2: per-edge combine on fp16 partials. One warp per edge, x2 ILP.
// ---------------------------------------------------------------------------
__global__ void __launch_bounds__(256)
edge_decode_kernel(const int* __restrict__ edges_gd, const int* __restrict__ edges_gg,
                   const float* __restrict__ w2_gd, const float* __restrict__ b2_gd,
                   const float* __restrict__ w2_gg, const float* __restrict__ b2_gg,
                   float* __restrict__ out, int E, int n_gene, int n_dis)
{
    const int rel = blockIdx.y;
    const size_t ng = (size_t)n_gene * H;
    const size_t nd = (size_t)n_dis * H;

    const int*   edges = rel ? edges_gg : edges_gd;
    const __half* Psrc = rel ? (g_Ph + ng + nd)      : g_Ph;
    const __half* Pdst = rel ? (g_Ph + ng + nd + ng) : (g_Ph + ng);
    const float* w2    = rel ? w2_gg : w2_gd;
    const float  b2    = (rel ? b2_gg : b2_gd)[0];
    float* o = out + (size_t)rel * E;

    const int lane   = threadIdx.x & 31;
    const int warp   = (blockIdx.x * blockDim.x + threadIdx.x) >> 5;
    const int nwarps = (gridDim.x * blockDim.x) >> 5;

    const float4 w = *(const float4*)&w2[lane * 4];

    for (int e = warp; e < E; e += 2 * nwarps) {
        const int e1 = e + nwarps;
        const bool has2 = e1 < E;

        const int s0 = edges[e], d0 = edges[E + e];
        uint2 ua0 = *(const uint2*)&Psrc[(size_t)s0 * H + lane * 4];
        uint2 ub0 = *(const uint2*)&Pdst[(size_t)d0 * H + lane * 4];

        uint2 ua1 = make_uint2(0u, 0u), ub1 = ua1;
        if (has2) {
            const int s1 = edges[e1], d1 = edges[E + e1];
            ua1 = *(const uint2*)&Psrc[(size_t)s1 * H + lane * 4];
            ub1 = *(const uint2*)&Pdst[(size_t)d1 * H + lane * 4];
        }

        float2 fa0 = __half22float2(*(__half2*)&ua0.x);
        float2 fa1 = __half22float2(*(__half2*)&ua0.y);
        float2 fb0 = __half22float2(*(__half2*)&ub0.x);
        float2 fb1 = __half22float2(*(__half2*)&ub0.y);
        float sum0;
        sum0  = fmaxf(fa0.x + fb0.x, 0.f) * w.x;
        sum0 += fmaxf(fa0.y + fb0.y, 0.f) * w.y;
        sum0 += fmaxf(fa1.x + fb1.x, 0.f) * w.z;
        sum0 += fmaxf(fa1.y + fb1.y, 0.f) * w.w;
        #pragma unroll
        for (int off = 16; off; off >>= 1)
            sum0 += __shfl_xor_sync(0xFFFFFFFFu, sum0, off);
        if (lane == 0) o[e] = sum0 + b2;

        if (has2) {
            float2 ga0 = __half22float2(*(__half2*)&ua1.x);
            float2 ga1 = __half22float2(*(__half2*)&ua1.y);
            float2 gb0 = __half22float2(*(__half2*)&ub1.x);
            float2 gb1 = __half22float2(*(__half2*)&ub1.y);
            float sum1;
            sum1  = fmaxf(ga0.x + gb0.x, 0.f) * w.x;
            sum1 += fmaxf(ga0.y + gb0.y, 0.f) * w.y;
            sum1 += fmaxf(ga1.x + gb1.x, 0.f) * w.z;
            sum1 += fmaxf(ga1.y + gb1.y, 0.f) * w.w;
            #pragma unroll
            for (int off = 16; off; off >>= 1)
                sum1 += __shfl_xor_sync(0xFFFFFFFFu, sum1, off);
            if (lane == 0) o[e1] = sum1 + b2;
        }
    }
}

// ---------------------------------------------------------------------------
extern "C" void kernel_launch(void* const* d_in, const int* in_sizes, int n_in,
                              void* d_out, int out_size)
{
    const float* z_gene = (const float*)d_in[0];
    const float* z_dis  = (const float*)d_in[1];
    const int*   e_gd   = (const int*)  d_in[2];
    const int*   e_gg   = (const int*)  d_in[3];
    const float* w1_gd  = (const float*)d_in[4];
    const float* b1_gd  = (const float*)d_in[5];
    const float* w2_gd  = (const float*)d_in[6];
    const float* b2_gd  = (const float*)d_in[7];
    const float* w1_gg  = (const float*)d_in[8];
    const float* b1_gg  = (const float*)d_in[9];
    const float* w2_gg  = (const float*)d_in[10];
    const float* b2_gg  = (const float*)d_in[11];

    const int n_gene = in_sizes[0] / H;
    const int n_dis  = in_sizes[1] / H;
    const int E      = in_sizes[2] / 2;

    static bool init_done = false;
    if (!init_done) {
        cudaFuncSetAttribute(gemm_tc_kernel,
                             cudaFuncAttributeMaxDynamicSharedMemorySize, SM_TOTAL);
        init_done = true;
    }

    prep_w_kernel<<<(4 * H * H + 255) / 256, 256>>>(w1_gd, w1_gg);

    const int tg = (n_gene + 127) >> 7;
    const int td = (n_dis + 127) >> 7;
    gemm_tc_kernel<<<tg + td, 512, SM_TOTAL>>>(z_gene, z_dis, b1_gd, b1_gg,
                                               n_gene, n_dis);

    dim3 egrid(1184, 2);
    edge_decode_kernel<<<egrid, 256>>>(e_gd, e_gg, w2_gd, b2_gd, w2_gg, b2_gg,
                                       (float*)d_out, E, n_gene, n_dis);
}